// round 6
// baseline (speedup 1.0000x reference)
#include <cuda_runtime.h>
#include <cuda_bf16.h>
#include <math.h>

// ---------------------------------------------------------------------------
// Problem constants
// ---------------------------------------------------------------------------
#define TT   1024
#define TOPK 256
#define NEGF (-1e30f)

// ---------------------------------------------------------------------------
// Scratch (device globals; no cudaMalloc allowed)
// ---------------------------------------------------------------------------
#define OFF_QLAT   0UL                         // 1024*1536
#define OFF_CKV    1572864UL                   // 1024*576
#define OFF_SKV    2162688UL                   // 1025*576
#define OFF_QI     2753088UL                   // 1024*2048
#define OFF_KI     4850240UL                   // 1024*128
#define OFF_W      4981312UL                   // 1024*16
#define OFF_SCORE  4997696UL                   // 1024*1024
#define OFF_IDX    6046272UL                   // 1024*256 (ints)
#define OFF_QFULL  6308416UL                   // 1024*3072
#define OFF_SQ     9454144UL                   // 1024*16*576
#define OFF_ATTN   18891328UL                  // 1024*16*512
#define OFF_O      27279936UL                  // 1024*2048
#define SCRATCH_FLOATS 29377088UL

__device__ float g_scratch[SCRATCH_FLOATS];

// ---------------------------------------------------------------------------
// fp64 block reduction for norm statistics
// ---------------------------------------------------------------------------
__device__ __forceinline__ double block_reduce_sum_d(double v, double* sm) {
    int lane = threadIdx.x & 31, wid = threadIdx.x >> 5;
#pragma unroll
    for (int o = 16; o > 0; o >>= 1) v += __shfl_xor_sync(0xffffffffu, v, o);
    if (lane == 0) sm[wid] = v;
    __syncthreads();
    int nw = (blockDim.x + 31) >> 5;
    double r = (threadIdx.x < nw) ? sm[threadIdx.x] : 0.0;
#pragma unroll
    for (int o = 16; o > 0; o >>= 1) r += __shfl_xor_sync(0xffffffffu, r, o);
    if (threadIdx.x == 0) sm[0] = r;
    __syncthreads();
    r = sm[0];
    __syncthreads();
    return r;
}

__device__ __forceinline__ float rsqrt_exact(float x) {
    return __fdiv_rn(1.0f, __fsqrt_rn(x));
}

// ---------------------------------------------------------------------------
// Generic tiled GEMM, templated accumulator type (float or double).
//   BT=true : C[m,n] = sum_k A[m,k]*B[n,k]
//   BT=false: C[m,n] = sum_k A[m,k]*B[k,n]
// fp32 inputs; AccT accumulation; f32 store.
// ---------------------------------------------------------------------------
template<bool BT, typename AccT>
__global__ __launch_bounds__(256)
void sgemm_kernel(const float* __restrict__ A, const float* __restrict__ B,
                  float* __restrict__ C,
                  int M, int N, int K, int lda, int ldb, int ldc,
                  long long sA, long long sB, long long sC) {
    __shared__ float As[16 * 68];   // [k][m] padded
    __shared__ float Bs[16 * 68];   // [k][n] padded
    long long bz = blockIdx.z;
    A += bz * sA; B += bz * sB; C += bz * sC;
    int m0 = blockIdx.y * 64, n0 = blockIdx.x * 64;
    int tid = threadIdx.x;
    int tx = tid & 15, ty = tid >> 4;
    AccT acc[4][4];
#pragma unroll
    for (int i = 0; i < 4; i++)
#pragma unroll
        for (int j = 0; j < 4; j++) acc[i][j] = (AccT)0;
    for (int k0 = 0; k0 < K; k0 += 16) {
#pragma unroll
        for (int i = 0; i < 4; i++) {
            int e = tid + i * 256;
            int m = e >> 4, kk = e & 15;
            float v = 0.f;
            if (m0 + m < M) v = A[(long long)(m0 + m) * lda + k0 + kk];
            As[kk * 68 + m] = v;
        }
#pragma unroll
        for (int i = 0; i < 4; i++) {
            int e = tid + i * 256;
            float v = 0.f;
            if (BT) {
                int n = e >> 4, kk = e & 15;
                if (n0 + n < N) v = B[(long long)(n0 + n) * ldb + k0 + kk];
                Bs[kk * 68 + n] = v;
            } else {
                int kk = e >> 6, n = e & 63;
                if (n0 + n < N) v = B[(long long)(k0 + kk) * ldb + n0 + n];
                Bs[kk * 68 + n] = v;
            }
        }
        __syncthreads();
#pragma unroll
        for (int kk = 0; kk < 16; kk++) {
            AccT a[4], b[4];
#pragma unroll
            for (int i = 0; i < 4; i++) a[i] = (AccT)As[kk * 68 + ty * 4 + i];
#pragma unroll
            for (int j = 0; j < 4; j++) b[j] = (AccT)Bs[kk * 68 + tx * 4 + j];
#pragma unroll
            for (int i = 0; i < 4; i++)
#pragma unroll
                for (int j = 0; j < 4; j++)
                    acc[i][j] = fma(a[i], b[j], acc[i][j]);
        }
        __syncthreads();
    }
#pragma unroll
    for (int i = 0; i < 4; i++) {
        int m = m0 + ty * 4 + i;
        if (m >= M) continue;
#pragma unroll
        for (int j = 0; j < 4; j++) {
            int n = n0 + tx * 4 + j;
            if (n < N) C[(long long)m * ldc + n] = (float)acc[i][j];
        }
    }
}

// ---------------------------------------------------------------------------
// RMSNorm rows in-place (fp64 stats, exact f32 epilogue)
// ---------------------------------------------------------------------------
__global__ void rms_kernel(float* x, const float* __restrict__ g, int N) {
    __shared__ double sm[8];
    int t = blockIdx.x;
    float* row = x + (size_t)t * N;
    double s = 0.0;
    for (int i = threadIdx.x; i < N; i += blockDim.x) { double v = row[i]; s += v * v; }
    s = block_reduce_sum_d(s, sm);
    float mean = __fdiv_rn((float)s, (float)N);
    float inv = rsqrt_exact(__fadd_rn(mean, 1e-6f));
    for (int i = threadIdx.x; i < N; i += blockDim.x)
        row[i] = __fmul_rn(__fmul_rn(row[i], inv), g[i]);
}

// ---------------------------------------------------------------------------
// Build skv[1025][576]
// ---------------------------------------------------------------------------
__global__ void kv_kernel(const float* __restrict__ ckv, const float* __restrict__ g,
                          const float* __restrict__ cosb, const float* __restrict__ sinb,
                          float* __restrict__ skv) {
    int t = blockIdx.x;
    if (t == TT) {
        for (int i = threadIdx.x; i < 576; i += blockDim.x) skv[(size_t)TT * 576 + i] = 0.f;
        return;
    }
    __shared__ double sm[8];
    const float* row = ckv + (size_t)t * 576;
    double s = 0.0;
    for (int i = threadIdx.x; i < 512; i += blockDim.x) { double v = row[i]; s += v * v; }
    s = block_reduce_sum_d(s, sm);
    float mean = __fdiv_rn((float)s, 512.f);
    float inv = rsqrt_exact(__fadd_rn(mean, 1e-6f));
    for (int i = threadIdx.x; i < 512; i += blockDim.x)
        skv[(size_t)t * 576 + i] = __fmul_rn(__fmul_rn(row[i], inv), g[i]);
    if (threadIdx.x < 64) {
        int i = threadIdx.x;
        float c = cosb[t * 64 + i], sn = sinb[t * 64 + i];
        float o;
        if (i < 32) o = __fsub_rn(__fmul_rn(row[512 + 2 * i], c), __fmul_rn(row[512 + 2 * i + 1], sn));
        else { int j = i - 32; o = __fadd_rn(__fmul_rn(row[512 + 2 * j + 1], c), __fmul_rn(row[512 + 2 * j], sn)); }
        skv[(size_t)t * 576 + 512 + i] = o;
    }
}

// ---------------------------------------------------------------------------
// In-place rope on first 64 dims of each 128-dim indexer head
// ---------------------------------------------------------------------------
__global__ void qirope_kernel(float* qi, const float* __restrict__ cosb,
                              const float* __restrict__ sinb) {
    int t = blockIdx.x;
    int h = threadIdx.x >> 5, lane = threadIdx.x & 31;
    float* p = qi + (size_t)t * 2048 + h * 128;
    float x0 = p[2 * lane], x1 = p[2 * lane + 1];
    float c0 = cosb[t * 64 + lane], s0 = sinb[t * 64 + lane];
    float c1 = cosb[t * 64 + 32 + lane], s1 = sinb[t * 64 + 32 + lane];
    __syncwarp();
    p[lane]      = __fsub_rn(__fmul_rn(x0, c0), __fmul_rn(x1, s0));
    p[lane + 32] = __fadd_rn(__fmul_rn(x1, c1), __fmul_rn(x0, s1));
}

// ---------------------------------------------------------------------------
// In-place LayerNorm(128)+rope on ki rows (fp64 stats, exact f32 epilogue)
// ---------------------------------------------------------------------------
__global__ void ki_kernel(float* ki, const float* __restrict__ w, const float* __restrict__ b,
                          const float* __restrict__ cosb, const float* __restrict__ sinb) {
    __shared__ double sm[8];
    __shared__ float srow[128];
    int t = blockIdx.x, d = threadIdx.x;
    float* row = ki + (size_t)t * 128;
    float v = row[d];
    double msum = block_reduce_sum_d((double)v, sm);
    float m = __fdiv_rn((float)msum, 128.f);
    float dv = __fsub_rn(v, m);
    double vsum = block_reduce_sum_d((double)dv * (double)dv, sm);
    float var = __fdiv_rn((float)vsum, 128.f);
    float inv = rsqrt_exact(__fadd_rn(var, 1e-6f));
    float y = __fadd_rn(__fmul_rn(__fmul_rn(dv, inv), w[d]), b[d]);
    srow[d] = y;
    __syncthreads();
    float o;
    if (d < 32)
        o = __fsub_rn(__fmul_rn(srow[2 * d], cosb[t * 64 + d]), __fmul_rn(srow[2 * d + 1], sinb[t * 64 + d]));
    else if (d < 64) {
        int j = d - 32;
        o = __fadd_rn(__fmul_rn(srow[2 * j + 1], cosb[t * 64 + d]), __fmul_rn(srow[2 * j], sinb[t * 64 + d]));
    } else o = y;
    row[d] = o;
}

// ---------------------------------------------------------------------------
// Indexer score with fp64 logits dot and fp64 h-sum:
//   logit = (f32) [ fp64 sum_d qi*ki ] ; prod = relu(logit)*w (f32);
//   score = (f32)(fp64 sum_h prod) * scale
// ---------------------------------------------------------------------------
__global__ __launch_bounds__(256)
void score_kernel(const float* __restrict__ qi, const float* __restrict__ ki,
                  const float* __restrict__ wproj,
                  const int* __restrict__ ks, const int* __restrict__ ke,
                  float* __restrict__ score) {
    __shared__ float s_qi[16 * 129];
    __shared__ float s_ki[16 * 129];
    __shared__ float s_prod[16 * 16];   // [sl][h]
    int t = blockIdx.y, s0 = blockIdx.x * 16;
    int h = threadIdx.x & 15, sl = threadIdx.x >> 4;
    for (int e = threadIdx.x; e < 16 * 128; e += 256) {
        int r = e >> 7, c = e & 127;
        s_qi[r * 129 + c] = qi[(size_t)t * 2048 + r * 128 + c];
        s_ki[r * 129 + c] = ki[(size_t)(s0 + r) * 128 + c];
    }
    __syncthreads();
    double acc = 0.0;
#pragma unroll 8
    for (int d = 0; d < 128; d++)
        acc = fma((double)s_qi[h * 129 + d], (double)s_ki[sl * 129 + d], acc);
    float lg = (float)acc;
    s_prod[sl * 16 + h] = __fmul_rn(fmaxf(lg, 0.f), wproj[t * 16 + h]);
    __syncthreads();
    if (threadIdx.x < 16) {
        int s = s0 + threadIdx.x;
        double sum = 0.0;
#pragma unroll
        for (int hh = 0; hh < 16; hh++) sum += (double)s_prod[threadIdx.x * 16 + hh];
        float sc = __fmul_rn((float)sum, 0.022097086912079608f);   // (128*16)^-0.5
        if (s < ks[t] || s > ke[t]) sc = NEGF;
        score[(size_t)t * TT + s] = sc;
    }
}

// ---------------------------------------------------------------------------
// Top-256 per row via bitonic sort of packed (value desc, index asc) u64 keys.
// ---------------------------------------------------------------------------
__global__ __launch_bounds__(512)
void topk_kernel(const float* __restrict__ score, int* __restrict__ out) {
    __shared__ unsigned long long keys[TT];
    int t = blockIdx.x;
    const float* row = score + (size_t)t * TT;
    for (int i = threadIdx.x; i < TT; i += 512) {
        unsigned u = __float_as_uint(row[i]);
        if (u == 0x80000000u) u = 0u;   // -0.0 == +0.0 tie semantics
        u = (u & 0x80000000u) ? ~u : (u | 0x80000000u);
        keys[i] = ((unsigned long long)(~u) << 32) | (unsigned)i;
    }
    __syncthreads();
    for (int k = 2; k <= TT; k <<= 1) {
        for (int j = k >> 1; j > 0; j >>= 1) {
            for (int i = threadIdx.x; i < TT; i += 512) {
                int ixj = i ^ j;
                if (ixj > i) {
                    bool up = ((i & k) == 0);
                    unsigned long long a = keys[i], c = keys[ixj];
                    if ((a > c) == up) { keys[i] = c; keys[ixj] = a; }
                }
            }
            __syncthreads();
        }
    }
    if (threadIdx.x < TOPK) {
        int idx = (int)(keys[threadIdx.x] & 0xffffffffu);
        float v = score[(size_t)t * TT + idx];
        out[t * TOPK + threadIdx.x] = (v <= -5e29f) ? TT : idx;
    }
}

// ---------------------------------------------------------------------------
// Fill sq[t,h,512:576] = rope(q_full[t, h*192+128 : h*192+192])
// ---------------------------------------------------------------------------
__global__ void sqrope_kernel(const float* __restrict__ qfull, const float* __restrict__ cosb,
                              const float* __restrict__ sinb, float* __restrict__ sq) {
    int t = blockIdx.x;
    int h = threadIdx.x >> 5, lane = threadIdx.x & 31;
    const float* p = qfull + (size_t)t * 3072 + h * 192 + 128;
    float x0 = p[2 * lane], x1 = p[2 * lane + 1];
    float* o = sq + ((size_t)t * 16 + h) * 576 + 512;
    o[lane]      = __fsub_rn(__fmul_rn(x0, cosb[t * 64 + lane]), __fmul_rn(x1, sinb[t * 64 + lane]));
    o[lane + 32] = __fadd_rn(__fmul_rn(x1, cosb[t * 64 + 32 + lane]), __fmul_rn(x0, sinb[t * 64 + 32 + lane]));
}

// ---------------------------------------------------------------------------
// Gathered sparse attention per t (exact fp32; smooth in indices)
// ---------------------------------------------------------------------------
#define ATT_SMEM ((16*577*2 + 16*256) * 4 + 256 * 4)
__global__ __launch_bounds__(256)
void attn_kernel(const float* __restrict__ sq, const float* __restrict__ skv,
                 const int* __restrict__ idxs, float* __restrict__ out) {
    extern __shared__ float sm[];
    float* s_sq = sm;                 // 16*577
    float* s_kv = sm + 16 * 577;      // 16*577
    float* s_p  = sm + 2 * 16 * 577;  // 16*256
    int*   s_idx = (int*)(s_p + 16 * 256);
    int t = blockIdx.x, tid = threadIdx.x;

    s_idx[tid] = idxs[t * TOPK + tid];
    for (int e = tid; e < 16 * 576; e += 256) {
        int r = e / 576, c = e - r * 576;
        s_sq[r * 577 + c] = sq[(size_t)t * (16 * 576) + e];
    }

    int h = tid >> 4, jl = tid & 15;
    float lreg[16];
    const float qscale = 0.07216878364870323f;   // 192^-0.5

    for (int jb = 0; jb < 16; jb++) {
        __syncthreads();
        for (int e = tid; e < 16 * 576; e += 256) {
            int r = e / 576, c = e - r * 576;
            int gi = s_idx[jb * 16 + r];
            s_kv[r * 577 + c] = skv[(size_t)gi * 576 + c];
        }
        __syncthreads();
        float acc = 0.f;
#pragma unroll 8
        for (int d = 0; d < 576; d++) acc = fmaf(s_sq[h * 577 + d], s_kv[jl * 577 + d], acc);
        int j = jb * 16 + jl;
        lreg[jb] = (s_idx[j] == TT) ? NEGF : acc * qscale;
    }

    float mx = NEGF;
#pragma unroll
    for (int jb = 0; jb < 16; jb++) mx = fmaxf(mx, lreg[jb]);
#pragma unroll
    for (int o = 8; o > 0; o >>= 1) mx = fmaxf(mx, __shfl_xor_sync(0xffffffffu, mx, o, 16));
    float sum = 0.f;
#pragma unroll
    for (int jb = 0; jb < 16; jb++) { lreg[jb] = expf(lreg[jb] - mx); sum += lreg[jb]; }
#pragma unroll
    for (int o = 8; o > 0; o >>= 1) sum += __shfl_xor_sync(0xffffffffu, sum, o, 16);
    float inv = 1.f / sum;
#pragma unroll
    for (int jb = 0; jb < 16; jb++) s_p[h * 256 + jb * 16 + jl] = lreg[jb] * inv;

    int kl = jl;
    float acc2[32];
#pragma unroll
    for (int i = 0; i < 32; i++) acc2[i] = 0.f;
    for (int jb = 0; jb < 16; jb++) {
        __syncthreads();
        for (int e = tid; e < 16 * 576; e += 256) {
            int r = e / 576, c = e - r * 576;
            int gi = s_idx[jb * 16 + r];
            s_kv[r * 577 + c] = skv[(size_t)gi * 576 + c];
        }
        __syncthreads();
#pragma unroll 4
        for (int jj = 0; jj < 16; jj++) {
            float pj = s_p[h * 256 + jb * 16 + jj];
#pragma unroll
            for (int kk = 0; kk < 32; kk++)
                acc2[kk] = fmaf(pj, s_kv[jj * 577 + kk * 16 + kl], acc2[kk]);
        }
    }
    size_t base = ((size_t)t * 16 + h) * 512;
#pragma unroll
    for (int kk = 0; kk < 32; kk++) out[base + kk * 16 + kl] = acc2[kk];
}

// ---------------------------------------------------------------------------
// Host launcher
// ---------------------------------------------------------------------------
extern "C" void kernel_launch(void* const* d_in, const int* in_sizes, int n_in,
                              void* d_out, int out_size) {
    const float* hidden  = (const float*)d_in[0];
    const float* cosb    = (const float*)d_in[1];
    const float* sinb    = (const float*)d_in[2];
    const int*   ks      = (const int*)d_in[3];
    const int*   ke      = (const int*)d_in[4];
    const float* w_qa    = (const float*)d_in[5];
    const float* g_qa    = (const float*)d_in[6];
    const float* w_qb    = (const float*)d_in[7];
    const float* w_kva   = (const float*)d_in[8];
    const float* g_kva   = (const float*)d_in[9];
    const float* w_kvb   = (const float*)d_in[10];
    const float* w_o     = (const float*)d_in[11];
    const float* i_wqb   = (const float*)d_in[12];
    const float* i_wk    = (const float*)d_in[13];
    const float* i_ln_w  = (const float*)d_in[14];
    const float* i_ln_b  = (const float*)d_in[15];
    const float* i_wproj = (const float*)d_in[16];
    float* out = (float*)d_out;

    void* basev = nullptr;
    cudaGetSymbolAddress(&basev, g_scratch);
    float* base = (float*)basev;
    float* qlat   = base + OFF_QLAT;
    float* ckv    = base + OFF_CKV;
    float* skv    = base + OFF_SKV;
    float* qi     = base + OFF_QI;
    float* ki     = base + OFF_KI;
    float* wbuf   = base + OFF_W;
    float* score  = base + OFF_SCORE;
    int*   idxb   = (int*)(base + OFF_IDX);
    float* qfull  = base + OFF_QFULL;
    float* sq     = base + OFF_SQ;
    float* attnb  = base + OFF_ATTN;
    float* obuf   = base + OFF_O;

    cudaFuncSetAttribute(attn_kernel, cudaFuncAttributeMaxDynamicSharedMemorySize, ATT_SMEM);

    dim3 blk(256);
    // ---- score-determining path: fp64-accumulated GEMMs ----
    sgemm_kernel<true, double><<<dim3(24, 16, 1), blk>>>(hidden, w_qa, qlat, 1024, 1536, 2048,
                                                         2048, 2048, 1536, 0, 0, 0);
    rms_kernel<<<1024, 256>>>(qlat, g_qa, 1536);
    sgemm_kernel<true, double><<<dim3(32, 16, 1), blk>>>(qlat, i_wqb, qi, 1024, 2048, 1536,
                                                         1536, 1536, 2048, 0, 0, 0);
    qirope_kernel<<<1024, 512>>>(qi, cosb, sinb);
    sgemm_kernel<true, double><<<dim3(2, 16, 1), blk>>>(hidden, i_wk, ki, 1024, 128, 2048,
                                                        2048, 2048, 128, 0, 0, 0);
    ki_kernel<<<1024, 128>>>(ki, i_ln_w, i_ln_b, cosb, sinb);
    sgemm_kernel<true, double><<<dim3(1, 16, 1), blk>>>(hidden, i_wproj, wbuf, 1024, 16, 2048,
                                                        2048, 2048, 16, 0, 0, 0);
    score_kernel<<<dim3(64, 1024), blk>>>(qi, ki, wbuf, ks, ke, score);
    topk_kernel<<<1024, 512>>>(score, idxb);

    // ---- smooth value path: exact fp32 ----
    sgemm_kernel<true, float><<<dim3(9, 16, 1), blk>>>(hidden, w_kva, ckv, 1024, 576, 2048,
                                                       2048, 2048, 576, 0, 0, 0);
    kv_kernel<<<1025, 256>>>(ckv, g_kva, cosb, sinb, skv);
    sgemm_kernel<true, float><<<dim3(48, 16, 1), blk>>>(qlat, w_qb, qfull, 1024, 3072, 1536,
                                                        1536, 1536, 3072, 0, 0, 0);
    sgemm_kernel<false, float><<<dim3(8, 16, 16), blk>>>(qfull, w_kvb, sq, 1024, 512, 128,
                                                         3072, 512, 9216,
                                                         192, 256 * 512, 576);
    sqrope_kernel<<<1024, 512>>>(qfull, cosb, sinb, sq);
    attn_kernel<<<1024, 256, ATT_SMEM>>>(sq, skv, idxb, attnb);
    sgemm_kernel<true, float><<<dim3(2, 16, 16), blk>>>(attnb, w_kvb + 128 * 512, obuf,
                                                        1024, 128, 512,
                                                        8192, 512, 2048,
                                                        512, 256 * 512, 128);
    sgemm_kernel<true, float><<<dim3(32, 16, 1), blk>>>(obuf, w_o, out, 1024, 2048, 2048,
                                                        2048, 2048, 2048, 0, 0, 0);
}

// round 7
// speedup vs baseline: 4.5155x; 4.5155x over previous
#include <cuda_runtime.h>
#include <cuda_bf16.h>
#include <math.h>

// ---------------------------------------------------------------------------
// Problem constants
// ---------------------------------------------------------------------------
#define TT   1024
#define TOPK 256
#define NEGF (-1e30f)

// ---------------------------------------------------------------------------
// Scratch (device globals; no cudaMalloc allowed)
// ---------------------------------------------------------------------------
#define OFF_QLAT   0UL                         // 1024*1536
#define OFF_CKV    1572864UL                   // 1024*576
#define OFF_SKV    2162688UL                   // 1025*576
#define OFF_QI     2753088UL                   // 1024*2048
#define OFF_KI     4850240UL                   // 1024*128
#define OFF_W      4981312UL                   // 1024*16
#define OFF_SCORE  4997696UL                   // 1024*1024
#define OFF_IDX    6046272UL                   // 1024*256 (ints)
#define OFF_QFULL  6308416UL                   // 1024*3072
#define OFF_SQ     9454144UL                   // 1024*16*576
#define OFF_ATTN   18891328UL                  // 1024*16*512
#define OFF_O      27279936UL                  // 1024*2048
#define SCRATCH_FLOATS 29377088UL

__device__ float g_scratch[SCRATCH_FLOATS];

// ---------------------------------------------------------------------------
// fp64 block reduction for norm statistics
// ---------------------------------------------------------------------------
__device__ __forceinline__ double block_reduce_sum_d(double v, double* sm) {
    int lane = threadIdx.x & 31, wid = threadIdx.x >> 5;
#pragma unroll
    for (int o = 16; o > 0; o >>= 1) v += __shfl_xor_sync(0xffffffffu, v, o);
    if (lane == 0) sm[wid] = v;
    __syncthreads();
    int nw = (blockDim.x + 31) >> 5;
    double r = (threadIdx.x < nw) ? sm[threadIdx.x] : 0.0;
#pragma unroll
    for (int o = 16; o > 0; o >>= 1) r += __shfl_xor_sync(0xffffffffu, r, o);
    if (threadIdx.x == 0) sm[0] = r;
    __syncthreads();
    r = sm[0];
    __syncthreads();
    return r;
}

__device__ __forceinline__ float rsqrt_exact(float x) {
    return __fdiv_rn(1.0f, __fsqrt_rn(x));
}

// ---------------------------------------------------------------------------
// Generic tiled GEMM.
//   BT=true : C[m,n] = sum_k A[m,k]*B[n,k]   BT=false: B is [K,N]
//   CHUNKD=false: plain fp32 FFMA chain (value path, matches ref fp32 GEMM)
//   CHUNKD=true : fp32 FFMA chains over 8-k chunks, folded into a double
//                 accumulator (score path: ~1.7e-7 relative error, no DFMA
//                 in the inner loop)
// ---------------------------------------------------------------------------
template<bool BT, bool CHUNKD>
__global__ __launch_bounds__(256)
void sgemm_kernel(const float* __restrict__ A, const float* __restrict__ B,
                  float* __restrict__ C,
                  int M, int N, int K, int lda, int ldb, int ldc,
                  long long sA, long long sB, long long sC) {
    __shared__ float As[16 * 68];   // [k][m] padded
    __shared__ float Bs[16 * 68];   // [k][n] padded
    long long bz = blockIdx.z;
    A += bz * sA; B += bz * sB; C += bz * sC;
    int m0 = blockIdx.y * 64, n0 = blockIdx.x * 64;
    int tid = threadIdx.x;
    int tx = tid & 15, ty = tid >> 4;

    float  accf[4][4];
    double accd[4][4];
#pragma unroll
    for (int i = 0; i < 4; i++)
#pragma unroll
        for (int j = 0; j < 4; j++) { accf[i][j] = 0.f; accd[i][j] = 0.0; }

    for (int k0 = 0; k0 < K; k0 += 16) {
#pragma unroll
        for (int i = 0; i < 4; i++) {
            int e = tid + i * 256;
            int m = e >> 4, kk = e & 15;
            float v = 0.f;
            if (m0 + m < M) v = A[(long long)(m0 + m) * lda + k0 + kk];
            As[kk * 68 + m] = v;
        }
#pragma unroll
        for (int i = 0; i < 4; i++) {
            int e = tid + i * 256;
            float v = 0.f;
            if (BT) {
                int n = e >> 4, kk = e & 15;
                if (n0 + n < N) v = B[(long long)(n0 + n) * ldb + k0 + kk];
                Bs[kk * 68 + n] = v;
            } else {
                int kk = e >> 6, n = e & 63;
                if (n0 + n < N) v = B[(long long)(k0 + kk) * ldb + n0 + n];
                Bs[kk * 68 + n] = v;
            }
        }
        __syncthreads();
        if (CHUNKD) {
#pragma unroll
            for (int c0 = 0; c0 < 16; c0 += 8) {
                float t[4][4];
#pragma unroll
                for (int i = 0; i < 4; i++)
#pragma unroll
                    for (int j = 0; j < 4; j++) t[i][j] = 0.f;
#pragma unroll
                for (int kk = c0; kk < c0 + 8; kk++) {
                    float a[4], b[4];
#pragma unroll
                    for (int i = 0; i < 4; i++) a[i] = As[kk * 68 + ty * 4 + i];
#pragma unroll
                    for (int j = 0; j < 4; j++) b[j] = Bs[kk * 68 + tx * 4 + j];
#pragma unroll
                    for (int i = 0; i < 4; i++)
#pragma unroll
                        for (int j = 0; j < 4; j++)
                            t[i][j] = fmaf(a[i], b[j], t[i][j]);
                }
#pragma unroll
                for (int i = 0; i < 4; i++)
#pragma unroll
                    for (int j = 0; j < 4; j++)
                        accd[i][j] += (double)t[i][j];
            }
        } else {
#pragma unroll
            for (int kk = 0; kk < 16; kk++) {
                float a[4], b[4];
#pragma unroll
                for (int i = 0; i < 4; i++) a[i] = As[kk * 68 + ty * 4 + i];
#pragma unroll
                for (int j = 0; j < 4; j++) b[j] = Bs[kk * 68 + tx * 4 + j];
#pragma unroll
                for (int i = 0; i < 4; i++)
#pragma unroll
                    for (int j = 0; j < 4; j++)
                        accf[i][j] = fmaf(a[i], b[j], accf[i][j]);
            }
        }
        __syncthreads();
    }
#pragma unroll
    for (int i = 0; i < 4; i++) {
        int m = m0 + ty * 4 + i;
        if (m >= M) continue;
#pragma unroll
        for (int j = 0; j < 4; j++) {
            int n = n0 + tx * 4 + j;
            if (n < N) C[(long long)m * ldc + n] = CHUNKD ? (float)accd[i][j] : accf[i][j];
        }
    }
}

// ---------------------------------------------------------------------------
// RMSNorm rows in-place (fp64 stats, exact f32 epilogue)
// ---------------------------------------------------------------------------
__global__ void rms_kernel(float* x, const float* __restrict__ g, int N) {
    __shared__ double sm[8];
    int t = blockIdx.x;
    float* row = x + (size_t)t * N;
    double s = 0.0;
    for (int i = threadIdx.x; i < N; i += blockDim.x) { double v = row[i]; s += v * v; }
    s = block_reduce_sum_d(s, sm);
    float mean = __fdiv_rn((float)s, (float)N);
    float inv = rsqrt_exact(__fadd_rn(mean, 1e-6f));
    for (int i = threadIdx.x; i < N; i += blockDim.x)
        row[i] = __fmul_rn(__fmul_rn(row[i], inv), g[i]);
}

// ---------------------------------------------------------------------------
// Build skv[1025][576]
// ---------------------------------------------------------------------------
__global__ void kv_kernel(const float* __restrict__ ckv, const float* __restrict__ g,
                          const float* __restrict__ cosb, const float* __restrict__ sinb,
                          float* __restrict__ skv) {
    int t = blockIdx.x;
    if (t == TT) {
        for (int i = threadIdx.x; i < 576; i += blockDim.x) skv[(size_t)TT * 576 + i] = 0.f;
        return;
    }
    __shared__ double sm[8];
    const float* row = ckv + (size_t)t * 576;
    double s = 0.0;
    for (int i = threadIdx.x; i < 512; i += blockDim.x) { double v = row[i]; s += v * v; }
    s = block_reduce_sum_d(s, sm);
    float mean = __fdiv_rn((float)s, 512.f);
    float inv = rsqrt_exact(__fadd_rn(mean, 1e-6f));
    for (int i = threadIdx.x; i < 512; i += blockDim.x)
        skv[(size_t)t * 576 + i] = __fmul_rn(__fmul_rn(row[i], inv), g[i]);
    if (threadIdx.x < 64) {
        int i = threadIdx.x;
        float c = cosb[t * 64 + i], sn = sinb[t * 64 + i];
        float o;
        if (i < 32) o = __fsub_rn(__fmul_rn(row[512 + 2 * i], c), __fmul_rn(row[512 + 2 * i + 1], sn));
        else { int j = i - 32; o = __fadd_rn(__fmul_rn(row[512 + 2 * j + 1], c), __fmul_rn(row[512 + 2 * j], sn)); }
        skv[(size_t)t * 576 + 512 + i] = o;
    }
}

// ---------------------------------------------------------------------------
// In-place rope on first 64 dims of each 128-dim indexer head
// ---------------------------------------------------------------------------
__global__ void qirope_kernel(float* qi, const float* __restrict__ cosb,
                              const float* __restrict__ sinb) {
    int t = blockIdx.x;
    int h = threadIdx.x >> 5, lane = threadIdx.x & 31;
    float* p = qi + (size_t)t * 2048 + h * 128;
    float x0 = p[2 * lane], x1 = p[2 * lane + 1];
    float c0 = cosb[t * 64 + lane], s0 = sinb[t * 64 + lane];
    float c1 = cosb[t * 64 + 32 + lane], s1 = sinb[t * 64 + 32 + lane];
    __syncwarp();
    p[lane]      = __fsub_rn(__fmul_rn(x0, c0), __fmul_rn(x1, s0));
    p[lane + 32] = __fadd_rn(__fmul_rn(x1, c1), __fmul_rn(x0, s1));
}

// ---------------------------------------------------------------------------
// In-place LayerNorm(128)+rope on ki rows (fp64 stats, exact f32 epilogue)
// ---------------------------------------------------------------------------
__global__ void ki_kernel(float* ki, const float* __restrict__ w, const float* __restrict__ b,
                          const float* __restrict__ cosb, const float* __restrict__ sinb) {
    __shared__ double sm[8];
    __shared__ float srow[128];
    int t = blockIdx.x, d = threadIdx.x;
    float* row = ki + (size_t)t * 128;
    float v = row[d];
    double msum = block_reduce_sum_d((double)v, sm);
    float m = __fdiv_rn((float)msum, 128.f);
    float dv = __fsub_rn(v, m);
    double vsum = block_reduce_sum_d((double)dv * (double)dv, sm);
    float var = __fdiv_rn((float)vsum, 128.f);
    float inv = rsqrt_exact(__fadd_rn(var, 1e-6f));
    float y = __fadd_rn(__fmul_rn(__fmul_rn(dv, inv), w[d]), b[d]);
    srow[d] = y;
    __syncthreads();
    float o;
    if (d < 32)
        o = __fsub_rn(__fmul_rn(srow[2 * d], cosb[t * 64 + d]), __fmul_rn(srow[2 * d + 1], sinb[t * 64 + d]));
    else if (d < 64) {
        int j = d - 32;
        o = __fadd_rn(__fmul_rn(srow[2 * j + 1], cosb[t * 64 + d]), __fmul_rn(srow[2 * j], sinb[t * 64 + d]));
    } else o = y;
    row[d] = o;
}

// ---------------------------------------------------------------------------
// Indexer score: 128-dot as fp32 chains over 8-chunks + double fold; h-sum fp64
// ---------------------------------------------------------------------------
__global__ __launch_bounds__(256)
void score_kernel(const float* __restrict__ qi, const float* __restrict__ ki,
                  const float* __restrict__ wproj,
                  const int* __restrict__ ks, const int* __restrict__ ke,
                  float* __restrict__ score) {
    __shared__ float s_qi[16 * 129];
    __shared__ float s_ki[16 * 129];
    __shared__ float s_prod[16 * 16];   // [sl][h]
    int t = blockIdx.y, s0 = blockIdx.x * 16;
    int h = threadIdx.x & 15, sl = threadIdx.x >> 4;
    for (int e = threadIdx.x; e < 16 * 128; e += 256) {
        int r = e >> 7, c = e & 127;
        s_qi[r * 129 + c] = qi[(size_t)t * 2048 + r * 128 + c];
        s_ki[r * 129 + c] = ki[(size_t)(s0 + r) * 128 + c];
    }
    __syncthreads();
    double acc = 0.0;
#pragma unroll
    for (int c0 = 0; c0 < 128; c0 += 8) {
        float tacc = 0.f;
#pragma unroll
        for (int d = c0; d < c0 + 8; d++)
            tacc = fmaf(s_qi[h * 129 + d], s_ki[sl * 129 + d], tacc);
        acc += (double)tacc;
    }
    float lg = (float)acc;
    s_prod[sl * 16 + h] = __fmul_rn(fmaxf(lg, 0.f), wproj[t * 16 + h]);
    __syncthreads();
    if (threadIdx.x < 16) {
        int s = s0 + threadIdx.x;
        double sum = 0.0;
#pragma unroll
        for (int hh = 0; hh < 16; hh++) sum += (double)s_prod[threadIdx.x * 16 + hh];
        float sc = __fmul_rn((float)sum, 0.022097086912079608f);   // (128*16)^-0.5
        if (s < ks[t] || s > ke[t]) sc = NEGF;
        score[(size_t)t * TT + s] = sc;
    }
}

// ---------------------------------------------------------------------------
// Top-256 per row via bitonic sort of packed (value desc, index asc) u64 keys.
// ---------------------------------------------------------------------------
__global__ __launch_bounds__(512)
void topk_kernel(const float* __restrict__ score, int* __restrict__ out) {
    __shared__ unsigned long long keys[TT];
    int t = blockIdx.x;
    const float* row = score + (size_t)t * TT;
    for (int i = threadIdx.x; i < TT; i += 512) {
        unsigned u = __float_as_uint(row[i]);
        if (u == 0x80000000u) u = 0u;   // -0.0 == +0.0 tie semantics
        u = (u & 0x80000000u) ? ~u : (u | 0x80000000u);
        keys[i] = ((unsigned long long)(~u) << 32) | (unsigned)i;
    }
    __syncthreads();
    for (int k = 2; k <= TT; k <<= 1) {
        for (int j = k >> 1; j > 0; j >>= 1) {
            for (int i = threadIdx.x; i < TT; i += 512) {
                int ixj = i ^ j;
                if (ixj > i) {
                    bool up = ((i & k) == 0);
                    unsigned long long a = keys[i], c = keys[ixj];
                    if ((a > c) == up) { keys[i] = c; keys[ixj] = a; }
                }
            }
            __syncthreads();
        }
    }
    if (threadIdx.x < TOPK) {
        int idx = (int)(keys[threadIdx.x] & 0xffffffffu);
        float v = score[(size_t)t * TT + idx];
        out[t * TOPK + threadIdx.x] = (v <= -5e29f) ? TT : idx;
    }
}

// ---------------------------------------------------------------------------
// Fill sq[t,h,512:576] = rope(q_full[t, h*192+128 : h*192+192])
// ---------------------------------------------------------------------------
__global__ void sqrope_kernel(const float* __restrict__ qfull, const float* __restrict__ cosb,
                              const float* __restrict__ sinb, float* __restrict__ sq) {
    int t = blockIdx.x;
    int h = threadIdx.x >> 5, lane = threadIdx.x & 31;
    const float* p = qfull + (size_t)t * 3072 + h * 192 + 128;
    float x0 = p[2 * lane], x1 = p[2 * lane + 1];
    float* o = sq + ((size_t)t * 16 + h) * 576 + 512;
    o[lane]      = __fsub_rn(__fmul_rn(x0, cosb[t * 64 + lane]), __fmul_rn(x1, sinb[t * 64 + lane]));
    o[lane + 32] = __fadd_rn(__fmul_rn(x1, cosb[t * 64 + 32 + lane]), __fmul_rn(x0, sinb[t * 64 + 32 + lane]));
}

// ---------------------------------------------------------------------------
// Gathered sparse attention per t (exact fp32; smooth in indices)
// ---------------------------------------------------------------------------
#define ATT_SMEM ((16*577*2 + 16*256) * 4 + 256 * 4)
__global__ __launch_bounds__(256)
void attn_kernel(const float* __restrict__ sq, const float* __restrict__ skv,
                 const int* __restrict__ idxs, float* __restrict__ out) {
    extern __shared__ float sm[];
    float* s_sq = sm;                 // 16*577
    float* s_kv = sm + 16 * 577;      // 16*577
    float* s_p  = sm + 2 * 16 * 577;  // 16*256
    int*   s_idx = (int*)(s_p + 16 * 256);
    int t = blockIdx.x, tid = threadIdx.x;

    s_idx[tid] = idxs[t * TOPK + tid];
    for (int e = tid; e < 16 * 576; e += 256) {
        int r = e / 576, c = e - r * 576;
        s_sq[r * 577 + c] = sq[(size_t)t * (16 * 576) + e];
    }

    int h = tid >> 4, jl = tid & 15;
    float lreg[16];
    const float qscale = 0.07216878364870323f;   // 192^-0.5

    for (int jb = 0; jb < 16; jb++) {
        __syncthreads();
        for (int e = tid; e < 16 * 576; e += 256) {
            int r = e / 576, c = e - r * 576;
            int gi = s_idx[jb * 16 + r];
            s_kv[r * 577 + c] = skv[(size_t)gi * 576 + c];
        }
        __syncthreads();
        float acc = 0.f;
#pragma unroll 8
        for (int d = 0; d < 576; d++) acc = fmaf(s_sq[h * 577 + d], s_kv[jl * 577 + d], acc);
        int j = jb * 16 + jl;
        lreg[jb] = (s_idx[j] == TT) ? NEGF : acc * qscale;
    }

    float mx = NEGF;
#pragma unroll
    for (int jb = 0; jb < 16; jb++) mx = fmaxf(mx, lreg[jb]);
#pragma unroll
    for (int o = 8; o > 0; o >>= 1) mx = fmaxf(mx, __shfl_xor_sync(0xffffffffu, mx, o, 16));
    float sum = 0.f;
#pragma unroll
    for (int jb = 0; jb < 16; jb++) { lreg[jb] = expf(lreg[jb] - mx); sum += lreg[jb]; }
#pragma unroll
    for (int o = 8; o > 0; o >>= 1) sum += __shfl_xor_sync(0xffffffffu, sum, o, 16);
    float inv = 1.f / sum;
#pragma unroll
    for (int jb = 0; jb < 16; jb++) s_p[h * 256 + jb * 16 + jl] = lreg[jb] * inv;

    int kl = jl;
    float acc2[32];
#pragma unroll
    for (int i = 0; i < 32; i++) acc2[i] = 0.f;
    for (int jb = 0; jb < 16; jb++) {
        __syncthreads();
        for (int e = tid; e < 16 * 576; e += 256) {
            int r = e / 576, c = e - r * 576;
            int gi = s_idx[jb * 16 + r];
            s_kv[r * 577 + c] = skv[(size_t)gi * 576 + c];
        }
        __syncthreads();
#pragma unroll 4
        for (int jj = 0; jj < 16; jj++) {
            float pj = s_p[h * 256 + jb * 16 + jj];
#pragma unroll
            for (int kk = 0; kk < 32; kk++)
                acc2[kk] = fmaf(pj, s_kv[jj * 577 + kk * 16 + kl], acc2[kk]);
        }
    }
    size_t base = ((size_t)t * 16 + h) * 512;
#pragma unroll
    for (int kk = 0; kk < 32; kk++) out[base + kk * 16 + kl] = acc2[kk];
}

// ---------------------------------------------------------------------------
// Host launcher
// ---------------------------------------------------------------------------
extern "C" void kernel_launch(void* const* d_in, const int* in_sizes, int n_in,
                              void* d_out, int out_size) {
    const float* hidden  = (const float*)d_in[0];
    const float* cosb    = (const float*)d_in[1];
    const float* sinb    = (const float*)d_in[2];
    const int*   ks      = (const int*)d_in[3];
    const int*   ke      = (const int*)d_in[4];
    const float* w_qa    = (const float*)d_in[5];
    const float* g_qa    = (const float*)d_in[6];
    const float* w_qb    = (const float*)d_in[7];
    const float* w_kva   = (const float*)d_in[8];
    const float* g_kva   = (const float*)d_in[9];
    const float* w_kvb   = (const float*)d_in[10];
    const float* w_o     = (const float*)d_in[11];
    const float* i_wqb   = (const float*)d_in[12];
    const float* i_wk    = (const float*)d_in[13];
    const float* i_ln_w  = (const float*)d_in[14];
    const float* i_ln_b  = (const float*)d_in[15];
    const float* i_wproj = (const float*)d_in[16];
    float* out = (float*)d_out;

    void* basev = nullptr;
    cudaGetSymbolAddress(&basev, g_scratch);
    float* base = (float*)basev;
    float* qlat   = base + OFF_QLAT;
    float* ckv    = base + OFF_CKV;
    float* skv    = base + OFF_SKV;
    float* qi     = base + OFF_QI;
    float* ki     = base + OFF_KI;
    float* wbuf   = base + OFF_W;
    float* score  = base + OFF_SCORE;
    int*   idxb   = (int*)(base + OFF_IDX);
    float* qfull  = base + OFF_QFULL;
    float* sq     = base + OFF_SQ;
    float* attnb  = base + OFF_ATTN;
    float* obuf   = base + OFF_O;

    cudaFuncSetAttribute(attn_kernel, cudaFuncAttributeMaxDynamicSharedMemorySize, ATT_SMEM);

    dim3 blk(256);
    // ---- score-determining path: chunked-double fp32 GEMMs ----
    sgemm_kernel<true, true><<<dim3(24, 16, 1), blk>>>(hidden, w_qa, qlat, 1024, 1536, 2048,
                                                       2048, 2048, 1536, 0, 0, 0);
    rms_kernel<<<1024, 256>>>(qlat, g_qa, 1536);
    sgemm_kernel<true, true><<<dim3(32, 16, 1), blk>>>(qlat, i_wqb, qi, 1024, 2048, 1536,
                                                       1536, 1536, 2048, 0, 0, 0);
    qirope_kernel<<<1024, 512>>>(qi, cosb, sinb);
    sgemm_kernel<true, true><<<dim3(2, 16, 1), blk>>>(hidden, i_wk, ki, 1024, 128, 2048,
                                                      2048, 2048, 128, 0, 0, 0);
    ki_kernel<<<1024, 128>>>(ki, i_ln_w, i_ln_b, cosb, sinb);
    sgemm_kernel<true, true><<<dim3(1, 16, 1), blk>>>(hidden, i_wproj, wbuf, 1024, 16, 2048,
                                                      2048, 2048, 16, 0, 0, 0);
    score_kernel<<<dim3(64, 1024), blk>>>(qi, ki, wbuf, ks, ke, score);
    topk_kernel<<<1024, 512>>>(score, idxb);

    // ---- smooth value path: exact fp32 ----
    sgemm_kernel<true, false><<<dim3(9, 16, 1), blk>>>(hidden, w_kva, ckv, 1024, 576, 2048,
                                                       2048, 2048, 576, 0, 0, 0);
    kv_kernel<<<1025, 256>>>(ckv, g_kva, cosb, sinb, skv);
    sgemm_kernel<true, false><<<dim3(48, 16, 1), blk>>>(qlat, w_qb, qfull, 1024, 3072, 1536,
                                                        1536, 1536, 3072, 0, 0, 0);
    sgemm_kernel<false, false><<<dim3(8, 16, 16), blk>>>(qfull, w_kvb, sq, 1024, 512, 128,
                                                         3072, 512, 9216,
                                                         192, 256 * 512, 576);
    sqrope_kernel<<<1024, 512>>>(qfull, cosb, sinb, sq);
    attn_kernel<<<1024, 256, ATT_SMEM>>>(sq, skv, idxb, attnb);
    sgemm_kernel<true, false><<<dim3(2, 16, 16), blk>>>(attnb, w_kvb + 128 * 512, obuf,
                                                        1024, 128, 512,
                                                        8192, 512, 2048,
                                                        512, 256 * 512, 128);
    sgemm_kernel<true, false><<<dim3(32, 16, 1), blk>>>(obuf, w_o, out, 1024, 2048, 2048,
                                                        2048, 2048, 2048, 0, 0, 0);
}